// round 15
// baseline (speedup 1.0000x reference)
#include <cuda_runtime.h>
#include <math.h>

// ---------------- problem constants ----------------
#define B_  8
#define N_  2048
#define D_  16
#define K_  8
#define SCALE_ 0.35355339059327373f     // hd^-0.5
#define LOG2E_ 1.4426950408889634f
#define MSPLIT_ 4

typedef unsigned long long ull;
typedef unsigned int uint32;

// ---------------- packed f32x2 helpers ----------------
#define FMA2(d, a, b, c) asm("fma.rn.f32x2 %0, %1, %2, %3;" : "=l"(d) : "l"(a), "l"(b), "l"(c))
__device__ __forceinline__ ull pack2(float lo, float hi) {
    ull r; asm("mov.b64 %0, {%1, %2};" : "=l"(r) : "f"(lo), "f"(hi)); return r;
}
__device__ __forceinline__ void unpack2(ull v, float& lo, float& hi) {
    asm("mov.b64 {%0, %1}, %2;" : "=f"(lo), "=f"(hi) : "l"(v));
}
__device__ __forceinline__ float ex2f(float x) {
    float r; asm("ex2.approx.f32 %0, %1;" : "=f"(r) : "f"(x)); return r;
}
__device__ __forceinline__ float rcpf(float x) {
    float r; asm("rcp.approx.f32 %0, %1;" : "=f"(r) : "f"(x)); return r;
}
__device__ __forceinline__ float fast_tanh(float x) {
    float e = ex2f(2.8853900817779268f * x);
    return fmaf(-2.f, rcpf(e + 1.f), 1.f);
}
__device__ __forceinline__ uint32 cvt_tf32(float x) {
    uint32 r; asm("cvt.rna.tf32.f32 %0, %1;" : "=r"(r) : "f"(x)); return r;
}
#define MMA_TF32(d0,d1,d2,d3,a0,a1,a2,a3,b0,b1) \
    asm volatile("mma.sync.aligned.m16n8k8.row.col.f32.tf32.tf32.f32 " \
        "{%0,%1,%2,%3},{%4,%5,%6,%7},{%8,%9},{%0,%1,%2,%3};" \
        : "+f"(d0),"+f"(d1),"+f"(d2),"+f"(d3) \
        : "r"(a0),"r"(a1),"r"(a2),"r"(a3),"r"(b0),"r"(b1))

// ---------------- scratch ----------------
__device__ float g_Q   [B_ * N_ * 32];
__device__ float g_Kt  [B_ * N_ * 32];
__device__ float g_Vt  [B_ * N_ * 16];
__device__ float g_att [B_ * N_ * D_];
__device__ float g_cand[(size_t)B_ * K_ * N_ * D_];
__device__ float g_oAcc[(size_t)B_ * N_ * 4 * 16];
__device__ float g_lAcc[B_ * N_ * 4];
__device__ float g_wsumAcc[B_ * D_];
__device__ float g_hypf[B_ * K_ * D_];
__device__ float g_fimraw[B_ * K_];

// ---------------- Cl(3,0,1) helpers ----------------
__device__ __forceinline__ float cayley_sign(int a, int b) {
    int neg = 0;
#pragma unroll
    for (int i = 0; i < 4; i++)
        if ((b >> i) & 1) neg ^= (__popc(a >> (i + 1)) & 1);
    if ((a & b) & 8) return 0.f;
    return neg ? -1.f : 1.f;
}
__device__ __forceinline__ float rev_sign(int i) {
    int p = __popc(i);
    return ((p * (p - 1) / 2) & 1) ? -1.f : 1.f;
}

// ---------------- kernel 1: Q/K/V projection (2 threads/row) + init ----------------
__global__ __launch_bounds__(128) void proj_kernel(const float* __restrict__ state,
                            const float* __restrict__ Wq, const float* __restrict__ bq,
                            const float* __restrict__ Wk, const float* __restrict__ bk,
                            const float* __restrict__ hyp,
                            const float* __restrict__ W_hyp,
                            const float* __restrict__ b_hyp) {
    __shared__ __align__(16) float sW[2][16][32], sb[2][32];
    int t = threadIdx.x;
    int gid = blockIdx.x * 128 + t;
    int row = gid >> 1;
    int half = gid & 1;
    if (half == 0) {
        float4 z = make_float4(0.f, 0.f, 0.f, 0.f);
        float4* oz = (float4*)g_oAcc;
#pragma unroll
        for (int i = 0; i < 16; i++) oz[row + i * 16384] = z;
        ((float4*)g_lAcc)[row] = z;
    }
    if (blockIdx.x == 0) {
        if (t < B_ * K_) g_fimraw[t] = 0.f;
        if (t < B_ * D_) g_wsumAcc[t] = 0.f;
        for (int i = t; i < B_ * K_ * D_; i += 128) {
            int bk_ = i >> 4, d = i & 15;
            float v = b_hyp[d];
#pragma unroll
            for (int c = 0; c < 4; c++) v = fmaf(hyp[bk_ * 4 + c], W_hyp[c * D_ + d], v);
            g_hypf[i] = v;
        }
    }
    for (int i = t; i < 512; i += 128) {
        sW[0][i >> 5][i & 31] = Wq[i];
        sW[1][i >> 5][i & 31] = Wk[i];
    }
    if (t < 32) { sb[0][t] = bq[t]; sb[1][t] = bk[t]; }
    __syncthreads();

    float s[16];
    const float4* sp = (const float4*)(state + (size_t)row * 16);
#pragma unroll
    for (int i = 0; i < 4; i++) { float4 v = sp[i]; s[4*i]=v.x; s[4*i+1]=v.y; s[4*i+2]=v.z; s[4*i+3]=v.w; }
    ull sd[16];
#pragma unroll
    for (int d = 0; d < 16; d++) sd[d] = pack2(s[d], s[d]);
    const float (*W)[32] = sW[half];
    const float* bb = sb[half];
    const float qs = SCALE_ * LOG2E_;
    float* outbase = half ? g_Kt : g_Q;
    float* qo = outbase + (size_t)row * 32;
#pragma unroll
    for (int c2 = 0; c2 < 16; c2++) {
        ull a = ((const ull*)bb)[c2];
#pragma unroll
        for (int d = 0; d < 16; d++)
            FMA2(a, sd[d], ((const ull*)&W[d][0])[c2], a);
        float v0, v1; unpack2(a, v0, v1);
        if (half == 0) { v0 *= qs; v1 *= qs; }
        qo[2*c2]   = __uint_as_float(cvt_tf32(v0));
        qo[2*c2+1] = __uint_as_float(cvt_tf32(v1));
    }
    if (half == 1) {
        float* vt = g_Vt + (size_t)row * 16;
#pragma unroll
        for (int d = 0; d < 16; d++) vt[d] = __uint_as_float(cvt_tf32(s[d]));
    }
}

// ---------------- kernel 2: attention via tf32 warp MMA, m-split 4, v4-red merge ----------------
__global__ __launch_bounds__(256) void attn_kernel() {
    int b    = blockIdx.y;
    int t    = threadIdx.x;
    int w    = t >> 5;
    int lane = t & 31;
    int gID  = lane >> 2;
    int tg   = lane & 3;
    int n0w  = blockIdx.x * 128 + w * 16;
    int mbase = blockIdx.z * (N_ / MSPLIT_);   // 512 keys per block

    // union: staging (6144 floats) during mainloop; transpose buffer (8704) after
    __shared__ __align__(16) float sBuf[8704];
    float* sKf = sBuf;                 // 16*256 = 4096 floats
    float* sVf = sBuf + 4096;          // 16*128 = 2048 floats

    uint32 qa[4][4];
    {
        const float* Qb = g_Q + ((size_t)b * N_ + n0w) * 32;
#pragma unroll
        for (int h = 0; h < 4; h++) {
            qa[h][0] = __float_as_uint(Qb[(gID    ) * 32 + h * 8 + tg    ]);
            qa[h][1] = __float_as_uint(Qb[(gID + 8) * 32 + h * 8 + tg    ]);
            qa[h][2] = __float_as_uint(Qb[(gID    ) * 32 + h * 8 + tg + 4]);
            qa[h][3] = __float_as_uint(Qb[(gID + 8) * 32 + h * 8 + tg + 4]);
        }
    }
    float o[4][2][4];
#pragma unroll
    for (int h = 0; h < 4; h++)
#pragma unroll
        for (int nt = 0; nt < 2; nt++)
#pragma unroll
            for (int r = 0; r < 4; r++) o[h][nt][r] = 0.f;
    float l[4][2];
#pragma unroll
    for (int h = 0; h < 4; h++) { l[h][0] = 0.f; l[h][1] = 0.f; }

#pragma unroll
    for (int mt = 0; mt < N_ / MSPLIT_ / 128; mt++) {
        int m0 = mbase + mt * 128;
        __syncthreads();
#pragma unroll
        for (int i = 0; i < 4; i++) {
            int idx = t + i * 256;
            int key = idx >> 3, c = idx & 7;
            float4 v = ((const float4*)(g_Kt + ((size_t)b * N_ + m0 + key) * 32))[c];
            int kt = key >> 3, k8 = key & 7;
            float vv[4] = {v.x, v.y, v.z, v.w};
#pragma unroll
            for (int e = 0; e < 4; e++) {
                int col = 4 * c + e, h = col >> 3, j = col & 7, r = j >> 2, jm = j & 3;
                sKf[(((kt * 4 + h) * 2 + r) << 5) + k8 * 4 + jm] = vv[e];
            }
        }
#pragma unroll
        for (int i = 0; i < 2; i++) {
            int idx = t + i * 256;
            int key = idx >> 2, cg = idx & 3;
            float4 v = ((const float4*)(g_Vt + ((size_t)b * N_ + m0 + key) * 16))[cg];
            int kt = key >> 3, k8 = key & 7, r = k8 >> 2, k4 = k8 & 3;
            float vv[4] = {v.x, v.y, v.z, v.w};
#pragma unroll
            for (int e = 0; e < 4; e++) {
                int dim = 4 * cg + e, nt = dim >> 3, nn = dim & 7;
                sVf[((((kt * 2 + nt) << 1) + r) << 5) + nn * 4 + k4] = vv[e];
            }
        }
        __syncthreads();
#pragma unroll 2
        for (int kt = 0; kt < 16; kt++) {
            uint32 vb00 = __float_as_uint(sVf[(((kt * 2 + 0) << 1) + 0) * 32 + lane]);
            uint32 vb01 = __float_as_uint(sVf[(((kt * 2 + 0) << 1) + 1) * 32 + lane]);
            uint32 vb10 = __float_as_uint(sVf[(((kt * 2 + 1) << 1) + 0) * 32 + lane]);
            uint32 vb11 = __float_as_uint(sVf[(((kt * 2 + 1) << 1) + 1) * 32 + lane]);
            int src  = (lane & ~3) | (tg >> 1);
            int src2 = src + 2;
#pragma unroll
            for (int h = 0; h < 4; h++) {
                uint32 kb0 = __float_as_uint(sKf[((kt * 4 + h) * 2 + 0) * 32 + lane]);
                uint32 kb1 = __float_as_uint(sKf[((kt * 4 + h) * 2 + 1) * 32 + lane]);
                float d0 = 0.f, d1 = 0.f, d2 = 0.f, d3 = 0.f;
                MMA_TF32(d0, d1, d2, d3, qa[h][0], qa[h][1], qa[h][2], qa[h][3], kb0, kb1);
                float p0 = ex2f(d0), p1 = ex2f(d1), p2 = ex2f(d2), p3 = ex2f(d3);
                l[h][0] += p0 + p1;
                l[h][1] += p2 + p3;
                float u00 = __shfl_sync(0xffffffffu, p0, src);
                float u01 = __shfl_sync(0xffffffffu, p1, src);
                float u10 = __shfl_sync(0xffffffffu, p2, src);
                float u11 = __shfl_sync(0xffffffffu, p3, src);
                float u20 = __shfl_sync(0xffffffffu, p0, src2);
                float u21 = __shfl_sync(0xffffffffu, p1, src2);
                float u30 = __shfl_sync(0xffffffffu, p2, src2);
                float u31 = __shfl_sync(0xffffffffu, p3, src2);
                bool odd = (tg & 1);
                uint32 pa0 = cvt_tf32(odd ? u01 : u00);
                uint32 pa1 = cvt_tf32(odd ? u11 : u10);
                uint32 pa2 = cvt_tf32(odd ? u21 : u20);
                uint32 pa3 = cvt_tf32(odd ? u31 : u30);
                MMA_TF32(o[h][0][0], o[h][0][1], o[h][0][2], o[h][0][3],
                         pa0, pa1, pa2, pa3, vb00, vb01);
                MMA_TF32(o[h][1][0], o[h][1][1], o[h][1][2], o[h][1][3],
                         pa0, pa1, pa2, pa3, vb10, vb11);
            }
        }
    }

    // ---- l merge (shuffle + 1 atomic per (row,h)) ----
#pragma unroll
    for (int h = 0; h < 4; h++) {
        float l0 = l[h][0], l1 = l[h][1];
        l0 += __shfl_xor_sync(0xffffffffu, l0, 1);
        l0 += __shfl_xor_sync(0xffffffffu, l0, 2);
        l1 += __shfl_xor_sync(0xffffffffu, l1, 1);
        l1 += __shfl_xor_sync(0xffffffffu, l1, 2);
        if (tg == 0) {
            atomicAdd(&g_lAcc[(b * N_ + n0w + gID    ) * 4 + h], l0);
            atomicAdd(&g_lAcc[(b * N_ + n0w + gID + 8) * 4 + h], l1);
        }
    }

    // ---- O merge: transpose via smem, then v4 vector reductions ----
    __syncthreads();                   // all warps done with sKf/sVf
    {
        float* sO = sBuf;              // [8 warps][16 rows x 68 (padded)]
        int base = w * 1088;
#pragma unroll
        for (int h = 0; h < 4; h++) {
#pragma unroll
            for (int nt = 0; nt < 2; nt++) {
                int off = h * 16 + nt * 8 + tg * 2;
                sO[base + gID * 68 + off]           = o[h][nt][0];
                sO[base + gID * 68 + off + 1]       = o[h][nt][1];
                sO[base + (gID + 8) * 68 + off]     = o[h][nt][2];
                sO[base + (gID + 8) * 68 + off + 1] = o[h][nt][3];
            }
        }
        __syncthreads();
#pragma unroll
        for (int i = 0; i < 2; i++) {
            int item = t + i * 256;            // 512 (row,h) items
            int row = item >> 2, h = item & 3;
            int w2 = row >> 4, r16 = row & 15;
            const float4* srcp = (const float4*)&sO[w2 * 1088 + r16 * 68 + h * 16];
            float* dst = g_oAcc + (((size_t)(b * N_ + blockIdx.x * 128 + row)) * 4 + h) * 16;
#pragma unroll
            for (int j = 0; j < 4; j++) {
                float4 v = srcp[j];
                asm volatile("red.global.add.v4.f32 [%0], {%1,%2,%3,%4};"
                             :: "l"(dst + j * 4), "f"(v.x), "f"(v.y), "f"(v.z), "f"(v.w)
                             : "memory");
            }
        }
    }
}

// ---------------- kernel 2b: attention epilogue ----------------
__global__ __launch_bounds__(128) void attn_epi(const float* __restrict__ v_gains) {
    int b = blockIdx.y;
    int t = threadIdx.x;
    int n = blockIdx.x * 128 + t;
    __shared__ float sW[4][16];
    float gain = 0.25f * v_gains[0];
    float att[16];
#pragma unroll
    for (int d = 0; d < 16; d++) att[d] = 0.f;
#pragma unroll
    for (int h = 0; h < 4; h++) {
        float inv = rcpf(g_lAcc[(b * N_ + n) * 4 + h]);
        const float4* op = (const float4*)(g_oAcc + (((size_t)(b * N_ + n)) * 4 + h) * 16);
#pragma unroll
        for (int i = 0; i < 4; i++) {
            float4 v = op[i];
            att[4*i]   = fmaf(v.x, inv, att[4*i]);
            att[4*i+1] = fmaf(v.y, inv, att[4*i+1]);
            att[4*i+2] = fmaf(v.z, inv, att[4*i+2]);
            att[4*i+3] = fmaf(v.w, inv, att[4*i+3]);
        }
    }
#pragma unroll
    for (int d = 0; d < 16; d++) att[d] *= gain;
    float4* ap = (float4*)(g_att + ((size_t)b * N_ + n) * 16);
#pragma unroll
    for (int i = 0; i < 4; i++)
        ap[i] = make_float4(att[4*i], att[4*i+1], att[4*i+2], att[4*i+3]);
    float w[16];
#pragma unroll
    for (int d = 0; d < 16; d++) {
        float v = att[d];
        v += __shfl_xor_sync(0xffffffffu, v, 1);
        v += __shfl_xor_sync(0xffffffffu, v, 2);
        v += __shfl_xor_sync(0xffffffffu, v, 4);
        v += __shfl_xor_sync(0xffffffffu, v, 8);
        v += __shfl_xor_sync(0xffffffffu, v, 16);
        w[d] = v;
    }
    if ((t & 31) == 0) {
#pragma unroll
        for (int d = 0; d < 16; d++) sW[t >> 5][d] = w[d];
    }
    __syncthreads();
    if (t < 16) {
        float s = sW[0][t] + sW[1][t] + sW[2][t] + sW[3][t];
        atomicAdd(&g_wsumAcc[b * 16 + t], s);
    }
}

// ---------------- kernel 3: candidates + fim partials ----------------
__global__ __launch_bounds__(256) void cand_kernel(const float* __restrict__ W_act,
                            const float* __restrict__ b_act) {
    int b = blockIdx.z, k = blockIdx.y, ch = blockIdx.x;
    __shared__ __align__(16) float W[16][16];
    __shared__ __align__(16) float bias[16];
    int t = threadIdx.x;
    W[t >> 4][t & 15] = W_act[(k * 16 + (t >> 4)) * 16 + (t & 15)];
    if (t < 16) bias[t] = b_act[k * 16 + t] + g_hypf[(b * K_ + k) * 16 + t];
    __syncthreads();
    int n = ch * 256 + t;
    float a[16];
    const float4* ap = (const float4*)(g_att + ((size_t)b * N_ + n) * 16);
#pragma unroll
    for (int i = 0; i < 4; i++) { float4 v = ap[i]; a[4*i]=v.x; a[4*i+1]=v.y; a[4*i+2]=v.z; a[4*i+3]=v.w; }
    ull ad[16];
#pragma unroll
    for (int d = 0; d < 16; d++) ad[d] = pack2(a[d], a[d]);
    float c[16], ss = 0.f;
#pragma unroll
    for (int e2 = 0; e2 < 8; e2++) {
        ull acc = ((const ull*)bias)[e2];
#pragma unroll
        for (int d = 0; d < 16; d++) FMA2(acc, ad[d], ((const ull*)&W[d][0])[e2], acc);
        float v0, v1; unpack2(acc, v0, v1);
        v0 = fast_tanh(v0); v1 = fast_tanh(v1);
        c[2*e2] = v0; c[2*e2+1] = v1;
        ss = fmaf(v0, v0, fmaf(v1, v1, ss));
    }
    float4* cp = (float4*)(g_cand + (((size_t)(b * K_ + k)) * N_ + n) * 16);
#pragma unroll
    for (int i = 0; i < 4; i++) cp[i] = make_float4(c[4*i], c[4*i+1], c[4*i+2], c[4*i+3]);
    ss *= (1.f / 16.f);
#pragma unroll
    for (int off = 16; off > 0; off >>= 1) ss += __shfl_xor_sync(0xffffffffu, ss, off);
    __shared__ float wsums[8];
    if ((t & 31) == 0) wsums[t >> 5] = ss;
    __syncthreads();
    if (t == 0) {
        float tot = 0.f;
#pragma unroll
        for (int i = 0; i < 8; i++) tot += wsums[i];
        atomicAdd(&g_fimraw[b * K_ + k], tot);
    }
}

// ---------------- kernel 4: fused small-math + weighted select + gates + norm ----------------
__global__ __launch_bounds__(256) void final_kernel(const float* __restrict__ state,
                            const float* __restrict__ hyp, const float* __restrict__ R_accum,
                            const float* __restrict__ W_ws, const float* __restrict__ b_ws,
                            const float* __restrict__ W_s1, const float* __restrict__ b_s1,
                            const float* __restrict__ W_s2, const float* __restrict__ b_s2,
                            const float* __restrict__ W_lift, const float* __restrict__ b_lift,
                            const float* __restrict__ rotors,
                            const float* __restrict__ Wg1, const float* __restrict__ bg1,
                            const float* __restrict__ Wg2, const float* __restrict__ bg2,
                            const float* __restrict__ Wc1, const float* __restrict__ bc1,
                            const float* __restrict__ Wc2, const float* __restrict__ bc2,
                            const float* __restrict__ norm_scale,
                            float* __restrict__ out_ns, float* __restrict__ out_newhyp,
                            float* __restrict__ out_R, float* __restrict__ out_fim,
                            float* __restrict__ out_w, float* __restrict__ out_gate) {
    int b = blockIdx.y;
    int bx = blockIdx.x;
    int t = threadIdx.x;
    int n = bx * 256 + t;

    __shared__ __align__(16) float sWg1[32][64];
    __shared__ __align__(16) float sWg2[64][16];
    __shared__ __align__(16) float sbg1[64], sbg2[16];
    __shared__ float sWc1[2][16], sbc1[16], sWc2[16], sns[16];
    __shared__ float sW1[640], sW2[320];
    __shared__ float sC[256];
    __shared__ float s_nh[8][4], s_logit[8], s_fim[8];
    __shared__ float s_w[8], s_agg[4], s_mod[16];
    __shared__ float s_Rt[16], s_Racc[16], s_Rn[16];
    __shared__ float sbc2, s_g0;

    for (int i = t; i < 2048; i += 256) sWg1[i >> 6][i & 63] = Wg1[i];
    for (int i = t; i < 1024; i += 256) sWg2[i >> 4][i & 15] = Wg2[i];
    for (int i = t; i < 640; i += 256) sW1[i] = W_s1[i];
    for (int i = t; i < 320; i += 256) sW2[i] = W_s2[i];
    sC[t] = cayley_sign(t >> 4, t & 15);
    if (t < 64) sbg1[t] = bg1[t];
    if (t < 16) { sbg2[t] = bg2[t]; sbc1[t] = bc1[t]; sWc2[t] = Wc2[t]; sns[t] = norm_scale[t]; }
    if (t < 32) sWc1[t >> 4][t & 15] = Wc1[t];
    if (t == 0) sbc2 = bc2[0];
    __syncthreads();

    const float invN = 1.f / (float)N_;
    if (t < 32) {
        int p = t >> 2;
        int q = t & 3;
        float fim = g_fimraw[b * 8 + p] * invN;
        float feat[10];
#pragma unroll
        for (int c = 0; c < 4; c++) feat[c] = hyp[(b * 8 + p) * 4 + c];
#pragma unroll
        for (int c = 0; c < 4; c++) {
            float v = b_ws[c];
#pragma unroll
            for (int d = 0; d < 16; d++)
                v = fmaf(g_wsumAcc[b * 16 + d] * invN, W_ws[d * 4 + c], v);
            feat[4 + c] = v;
        }
        feat[8] = fim; feat[9] = fim;
        float sp[5] = {0.f, 0.f, 0.f, 0.f, 0.f};
        for (int j = q; j < 64; j += 4) {
            float h = b_s1[j];
#pragma unroll
            for (int i = 0; i < 10; i++) h = fmaf(feat[i], sW1[i * 64 + j], h);
            h = fmaxf(h, 0.f);
#pragma unroll
            for (int c = 0; c < 5; c++) sp[c] = fmaf(h, sW2[j * 5 + c], sp[c]);
        }
#pragma unroll
        for (int c = 0; c < 5; c++) {
            sp[c] += __shfl_xor_sync(0xffffffffu, sp[c], 1);
            sp[c] += __shfl_xor_sync(0xffffffffu, sp[c], 2);
        }
        if (q == 0) {
            s_fim[p] = fim;
#pragma unroll
            for (int c = 0; c < 4; c++) s_nh[p][c] = feat[c] + sp[c] + b_s2[c];
            s_logit[p] = sp[4] + b_s2[4];
        }
        __syncwarp();
        if (t == 0) {
            float mx = -1e30f;
#pragma unroll
            for (int k = 0; k < 8; k++) mx = fmaxf(mx, s_logit[k]);
            float e[8], se = 0.f;
#pragma unroll
            for (int k = 0; k < 8; k++) { e[k] = __expf(s_logit[k] - mx); se += e[k]; }
            float inv = 1.f / se;
            float agg[4] = {0.f, 0.f, 0.f, 0.f};
#pragma unroll
            for (int k = 0; k < 8; k++) {
                float w = e[k] * inv;
                s_w[k] = w;
#pragma unroll
                for (int c = 0; c < 4; c++) agg[c] = fmaf(w, s_nh[k][c], agg[c]);
            }
#pragma unroll
            for (int c = 0; c < 4; c++) s_agg[c] = agg[c];
        }
        __syncwarp();
        if (t < 16) {
            float v = b_lift[t];
#pragma unroll
            for (int c = 0; c < 4; c++) v = fmaf(s_agg[c], W_lift[c * 16 + t], v);
            s_mod[t] = 1.f + tanhf(v);
        }
    }
    __syncthreads();

    if (bx == 0) {
        if (t < 8) { out_fim[b * 8 + t] = s_fim[t]; out_w[b * 8 + t] = s_w[t]; }
        if (t < 32) out_newhyp[b * 32 + t] = s_nh[t >> 2][t & 3];
        if (t < 16) {
            float v = 0.f;
#pragma unroll
            for (int k = 0; k < 8; k++) v = fmaf(s_w[k], rotors[k * 16 + t], v);
            s_Rt[t] = v;
            s_Racc[t] = R_accum[b * 16 + t];
        }
    }
    __syncthreads();
    if (bx == 0 && t < 16) {
        float v = 0.f;
#pragma unroll
        for (int a = 0; a < 16; a++) {
            int bb = a ^ t;
            v = fmaf(sC[a * 16 + bb] * s_Rt[a], s_Racc[bb], v);
        }
        s_Rn[t] = v;
    }
    __syncthreads();
    if (bx == 0 && t == 0) {
        float g0 = 0.f;
#pragma unroll
        for (int a = 0; a < 16; a++)
            g0 += sC[a * 16 + a] * s_Rn[a] * s_Rn[a] * rev_sign(a);
        s_g0 = rsqrtf(fmaxf(fabsf(g0), 1e-6f));
    }
    __syncthreads();
    if (bx == 0 && t < 16) out_R[b * 16 + t] = s_Rn[t] * s_g0;

    float in[32];
    const float4* sp = (const float4*)(state + ((size_t)b * N_ + n) * 16);
#pragma unroll
    for (int i = 0; i < 4; i++) { float4 v = sp[i]; in[4*i]=v.x; in[4*i+1]=v.y; in[4*i+2]=v.z; in[4*i+3]=v.w; }

    float ns_[16];
#pragma unroll
    for (int e = 0; e < 16; e++) ns_[e] = 0.f;
#pragma unroll
    for (int k = 0; k < 8; k++) {
        const float4* cp = (const float4*)(g_cand + (((size_t)(b * K_ + k)) * N_ + n) * 16);
        float wk = s_w[k];
#pragma unroll
        for (int i = 0; i < 4; i++) {
            float4 v = cp[i];
            ns_[4*i]   = fmaf(wk, v.x, ns_[4*i]);
            ns_[4*i+1] = fmaf(wk, v.y, ns_[4*i+1]);
            ns_[4*i+2] = fmaf(wk, v.z, ns_[4*i+2]);
            ns_[4*i+3] = fmaf(wk, v.w, ns_[4*i+3]);
        }
    }
#pragma unroll
    for (int e = 0; e < 16; e++) { ns_[e] *= s_mod[e]; in[16 + e] = ns_[e]; }

    ull accE[8];
#pragma unroll
    for (int e2 = 0; e2 < 8; e2++) accE[e2] = ((const ull*)sbg2)[e2];
#pragma unroll
    for (int half = 0; half < 2; half++) {
        ull accH[16];
#pragma unroll
        for (int j2 = 0; j2 < 16; j2++) accH[j2] = ((const ull*)sbg1)[half * 16 + j2];
#pragma unroll
        for (int i = 0; i < 32; i++) {
            ull ind = pack2(in[i], in[i]);
            const ull* wrow = (const ull*)&sWg1[i][half * 32];
#pragma unroll
            for (int j2 = 0; j2 < 16; j2++) FMA2(accH[j2], ind, wrow[j2], accH[j2]);
        }
#pragma unroll
        for (int j2 = 0; j2 < 16; j2++) {
            float h0, h1; unpack2(accH[j2], h0, h1);
            h0 = fmaxf(h0, 0.f); h1 = fmaxf(h1, 0.f);
            int j = half * 32 + j2 * 2;
            ull hd0 = pack2(h0, h0), hd1 = pack2(h1, h1);
            const ull* w0 = (const ull*)&sWg2[j][0];
            const ull* w1 = (const ull*)&sWg2[j + 1][0];
#pragma unroll
            for (int e2 = 0; e2 < 8; e2++) {
                FMA2(accE[e2], hd0, w0[e2], accE[e2]);
                FMA2(accE[e2], hd1, w1[e2], accE[e2]);
            }
        }
    }
    float gate[16];
#pragma unroll
    for (int e2 = 0; e2 < 8; e2++) {
        float a0, a1; unpack2(accE[e2], a0, a1);
        gate[2*e2]   = rcpf(1.f + ex2f(-LOG2E_ * a0));
        gate[2*e2+1] = rcpf(1.f + ex2f(-LOG2E_ * a1));
    }

    float cg = sbc2;
#pragma unroll
    for (int j = 0; j < 16; j++) {
        float h = fmaf(in[0], sWc1[0][j], fmaf(ns_[0], sWc1[1][j], sbc1[j]));
        h = fmaxf(h, 0.f);
        cg = fmaf(h, sWc2[j], cg);
    }
    cg = rcpf(1.f + ex2f(-LOG2E_ * cg));

    float val[16];
    val[0] = cg * ns_[0] + (1.f - cg) * in[0];
#pragma unroll
    for (int d = 1; d < 16; d++) val[d] = gate[d] * ns_[d] + (1.f - gate[d]) * in[d];

    float ms = 0.f;
#pragma unroll
    for (int d = 0; d < 16; d++) ms = fmaf(val[d], val[d], ms);
    float r = rsqrtf(ms * (1.f / 16.f) + 1e-6f);

    float4* no = (float4*)(out_ns + ((size_t)b * N_ + n) * 16);
    float4* go = (float4*)(out_gate + ((size_t)b * N_ + n) * 16);
#pragma unroll
    for (int i = 0; i < 4; i++) {
        no[i] = make_float4(val[4*i] * sns[4*i] * r, val[4*i+1] * sns[4*i+1] * r,
                            val[4*i+2] * sns[4*i+2] * r, val[4*i+3] * sns[4*i+3] * r);
        go[i] = make_float4(gate[4*i], gate[4*i+1], gate[4*i+2], gate[4*i+3]);
    }
}

// ---------------- launch ----------------
extern "C" void kernel_launch(void* const* d_in, const int* in_sizes, int n_in,
                              void* d_out, int out_size) {
    const float* state   = (const float*)d_in[0];
    const float* hyp     = (const float*)d_in[1];
    const float* R_accum = (const float*)d_in[2];
    const float* Wq = (const float*)d_in[4];
    const float* bq = (const float*)d_in[5];
    const float* Wk = (const float*)d_in[6];
    const float* bk = (const float*)d_in[7];
    const float* v_gains = (const float*)d_in[8];
    const float* W_act = (const float*)d_in[9];
    const float* b_act = (const float*)d_in[10];
    const float* W_hyp = (const float*)d_in[11];
    const float* b_hyp = (const float*)d_in[12];
    const float* W_ws = (const float*)d_in[13];
    const float* b_ws = (const float*)d_in[14];
    const float* W_s1 = (const float*)d_in[15];
    const float* b_s1 = (const float*)d_in[16];
    const float* W_s2 = (const float*)d_in[17];
    const float* b_s2 = (const float*)d_in[18];
    const float* W_lift = (const float*)d_in[19];
    const float* b_lift = (const float*)d_in[20];
    const float* Wg1 = (const float*)d_in[21];
    const float* bg1 = (const float*)d_in[22];
    const float* Wg2 = (const float*)d_in[23];
    const float* bg2 = (const float*)d_in[24];
    const float* Wc1 = (const float*)d_in[25];
    const float* bc1 = (const float*)d_in[26];
    const float* Wc2 = (const float*)d_in[27];
    const float* bc2 = (const float*)d_in[28];
    const float* norm_scale = (const float*)d_in[29];
    const float* rotors = (const float*)d_in[30];

    float* out = (float*)d_out;
    float* out_ns     = out;
    float* out_newhyp = out + (size_t)B_ * N_ * D_;
    float* out_R      = out_newhyp + B_ * K_ * 4;
    float* out_fim    = out_R + B_ * 16;
    float* out_w      = out_fim + B_ * K_;
    float* out_gate   = out_w + B_ * K_;

    proj_kernel<<<(B_ * N_ * 2) / 128, 128>>>(state, Wq, bq, Wk, bk, hyp, W_hyp, b_hyp);
    attn_kernel<<<dim3(N_ / 128, B_, MSPLIT_), 256>>>();
    attn_epi<<<dim3(N_ / 128, B_), 128>>>(v_gains);
    cand_kernel<<<dim3(N_ / 256, K_, B_), 256>>>(W_act, b_act);
    final_kernel<<<dim3(N_ / 256, B_), 256>>>(state, hyp, R_accum, W_ws, b_ws,
                                              W_s1, b_s1, W_s2, b_s2, W_lift, b_lift, rotors,
                                              Wg1, bg1, Wg2, bg2, Wc1, bc1, Wc2, bc2, norm_scale,
                                              out_ns, out_newhyp, out_R, out_fim, out_w, out_gate);
}

// round 16
// speedup vs baseline: 1.0868x; 1.0868x over previous
#include <cuda_runtime.h>
#include <math.h>

// ---------------- problem constants ----------------
#define B_  8
#define N_  2048
#define D_  16
#define K_  8
#define SCALE_ 0.35355339059327373f     // hd^-0.5
#define LOG2E_ 1.4426950408889634f
#define MSPLIT_ 8

typedef unsigned long long ull;
typedef unsigned int uint32;

// ---------------- packed f32x2 helpers ----------------
#define FMA2(d, a, b, c) asm("fma.rn.f32x2 %0, %1, %2, %3;" : "=l"(d) : "l"(a), "l"(b), "l"(c))
__device__ __forceinline__ ull pack2(float lo, float hi) {
    ull r; asm("mov.b64 %0, {%1, %2};" : "=l"(r) : "f"(lo), "f"(hi)); return r;
}
__device__ __forceinline__ void unpack2(ull v, float& lo, float& hi) {
    asm("mov.b64 {%0, %1}, %2;" : "=f"(lo), "=f"(hi) : "l"(v));
}
__device__ __forceinline__ float ex2f(float x) {
    float r; asm("ex2.approx.f32 %0, %1;" : "=f"(r) : "f"(x)); return r;
}
__device__ __forceinline__ float rcpf(float x) {
    float r; asm("rcp.approx.f32 %0, %1;" : "=f"(r) : "f"(x)); return r;
}
__device__ __forceinline__ float fast_tanh(float x) {
    float e = ex2f(2.8853900817779268f * x);
    return fmaf(-2.f, rcpf(e + 1.f), 1.f);
}
__device__ __forceinline__ uint32 cvt_tf32(float x) {
    uint32 r; asm("cvt.rna.tf32.f32 %0, %1;" : "=r"(r) : "f"(x)); return r;
}
#define MMA_TF32(d0,d1,d2,d3,a0,a1,a2,a3,b0,b1) \
    asm volatile("mma.sync.aligned.m16n8k8.row.col.f32.tf32.tf32.f32 " \
        "{%0,%1,%2,%3},{%4,%5,%6,%7},{%8,%9},{%0,%1,%2,%3};" \
        : "+f"(d0),"+f"(d1),"+f"(d2),"+f"(d3) \
        : "r"(a0),"r"(a1),"r"(a2),"r"(a3),"r"(b0),"r"(b1))

// ---------------- scratch ----------------
__device__ float g_Q   [B_ * N_ * 32];   // tf32-rounded, pre-scaled by SCALE*LOG2E
__device__ float g_Kt  [B_ * N_ * 32];   // tf32-rounded
__device__ float g_Vt  [B_ * N_ * 16];   // tf32-rounded state
__device__ float g_att [B_ * N_ * D_];
__device__ float g_cand[(size_t)B_ * K_ * N_ * D_];
__device__ float g_oAcc[(size_t)B_ * N_ * 4 * 16];
__device__ float g_lAcc[B_ * N_ * 4];
__device__ float g_wsumAcc[B_ * D_];
__device__ float g_hypf[B_ * K_ * D_];
__device__ float g_fimraw[B_ * K_];

// ---------------- Cl(3,0,1) helpers ----------------
__device__ __forceinline__ float cayley_sign(int a, int b) {
    int neg = 0;
#pragma unroll
    for (int i = 0; i < 4; i++)
        if ((b >> i) & 1) neg ^= (__popc(a >> (i + 1)) & 1);
    if ((a & b) & 8) return 0.f;
    return neg ? -1.f : 1.f;
}
__device__ __forceinline__ float rev_sign(int i) {
    int p = __popc(i);
    return ((p * (p - 1) / 2) & 1) ? -1.f : 1.f;
}

// ---------------- kernel 1: Q/K/V projection (2 threads/row) + init ----------------
__global__ __launch_bounds__(128) void proj_kernel(const float* __restrict__ state,
                            const float* __restrict__ Wq, const float* __restrict__ bq,
                            const float* __restrict__ Wk, const float* __restrict__ bk,
                            const float* __restrict__ hyp,
                            const float* __restrict__ W_hyp,
                            const float* __restrict__ b_hyp) {
    __shared__ __align__(16) float sW[2][16][32], sb[2][32];
    int t = threadIdx.x;
    int gid = blockIdx.x * 128 + t;
    int row = gid >> 1;
    int half = gid & 1;
    if (half == 0) {
        float4 z = make_float4(0.f, 0.f, 0.f, 0.f);
        float4* oz = (float4*)g_oAcc;
#pragma unroll
        for (int i = 0; i < 16; i++) oz[row + i * 16384] = z;
        ((float4*)g_lAcc)[row] = z;
    }
    if (blockIdx.x == 0) {
        if (t < B_ * K_) g_fimraw[t] = 0.f;
        if (t < B_ * D_) g_wsumAcc[t] = 0.f;
        for (int i = t; i < B_ * K_ * D_; i += 128) {
            int bk_ = i >> 4, d = i & 15;
            float v = b_hyp[d];
#pragma unroll
            for (int c = 0; c < 4; c++) v = fmaf(hyp[bk_ * 4 + c], W_hyp[c * D_ + d], v);
            g_hypf[i] = v;
        }
    }
    for (int i = t; i < 512; i += 128) {
        sW[0][i >> 5][i & 31] = Wq[i];
        sW[1][i >> 5][i & 31] = Wk[i];
    }
    if (t < 32) { sb[0][t] = bq[t]; sb[1][t] = bk[t]; }
    __syncthreads();

    float s[16];
    const float4* sp = (const float4*)(state + (size_t)row * 16);
#pragma unroll
    for (int i = 0; i < 4; i++) { float4 v = sp[i]; s[4*i]=v.x; s[4*i+1]=v.y; s[4*i+2]=v.z; s[4*i+3]=v.w; }
    ull sd[16];
#pragma unroll
    for (int d = 0; d < 16; d++) sd[d] = pack2(s[d], s[d]);
    const float (*W)[32] = sW[half];
    const float* bb = sb[half];
    const float qs = SCALE_ * LOG2E_;
    float* outbase = half ? g_Kt : g_Q;
    float* qo = outbase + (size_t)row * 32;
#pragma unroll
    for (int c2 = 0; c2 < 16; c2++) {
        ull a = ((const ull*)bb)[c2];
#pragma unroll
        for (int d = 0; d < 16; d++)
            FMA2(a, sd[d], ((const ull*)&W[d][0])[c2], a);
        float v0, v1; unpack2(a, v0, v1);
        if (half == 0) { v0 *= qs; v1 *= qs; }
        qo[2*c2]   = __uint_as_float(cvt_tf32(v0));
        qo[2*c2+1] = __uint_as_float(cvt_tf32(v1));
    }
    if (half == 1) {
        float* vt = g_Vt + (size_t)row * 16;
#pragma unroll
        for (int d = 0; d < 16; d++) vt[d] = __uint_as_float(cvt_tf32(s[d]));
    }
}

// ---------------- kernel 2: attention via tf32 warp MMA, m-split 8 (R14 geometry) ----------------
__global__ __launch_bounds__(256) void attn_kernel() {
    int b    = blockIdx.y;
    int t    = threadIdx.x;
    int w    = t >> 5;
    int lane = t & 31;
    int gID  = lane >> 2;
    int tg   = lane & 3;
    int n0w  = blockIdx.x * 128 + w * 16;
    int mbase = blockIdx.z * 256;

    __shared__ __align__(16) float sKf[16 * 256];
    __shared__ __align__(16) float sVf[16 * 128];

    uint32 qa[4][4];
    {
        const float* Qb = g_Q + ((size_t)b * N_ + n0w) * 32;
#pragma unroll
        for (int h = 0; h < 4; h++) {
            qa[h][0] = __float_as_uint(Qb[(gID    ) * 32 + h * 8 + tg    ]);
            qa[h][1] = __float_as_uint(Qb[(gID + 8) * 32 + h * 8 + tg    ]);
            qa[h][2] = __float_as_uint(Qb[(gID    ) * 32 + h * 8 + tg + 4]);
            qa[h][3] = __float_as_uint(Qb[(gID + 8) * 32 + h * 8 + tg + 4]);
        }
    }
    float o[4][2][4];
#pragma unroll
    for (int h = 0; h < 4; h++)
#pragma unroll
        for (int nt = 0; nt < 2; nt++)
#pragma unroll
            for (int r = 0; r < 4; r++) o[h][nt][r] = 0.f;
    float l[4][2];
#pragma unroll
    for (int h = 0; h < 4; h++) { l[h][0] = 0.f; l[h][1] = 0.f; }

#pragma unroll
    for (int mt = 0; mt < 2; mt++) {
        int m0 = mbase + mt * 128;
        __syncthreads();
#pragma unroll
        for (int i = 0; i < 4; i++) {
            int idx = t + i * 256;
            int key = idx >> 3, c = idx & 7;
            float4 v = ((const float4*)(g_Kt + ((size_t)b * N_ + m0 + key) * 32))[c];
            int kt = key >> 3, k8 = key & 7;
            float vv[4] = {v.x, v.y, v.z, v.w};
#pragma unroll
            for (int e = 0; e < 4; e++) {
                int col = 4 * c + e, h = col >> 3, j = col & 7, r = j >> 2, jm = j & 3;
                sKf[(((kt * 4 + h) * 2 + r) << 5) + k8 * 4 + jm] = vv[e];
            }
        }
#pragma unroll
        for (int i = 0; i < 2; i++) {
            int idx = t + i * 256;
            int key = idx >> 2, cg = idx & 3;
            float4 v = ((const float4*)(g_Vt + ((size_t)b * N_ + m0 + key) * 16))[cg];
            int kt = key >> 3, k8 = key & 7, r = k8 >> 2, k4 = k8 & 3;
            float vv[4] = {v.x, v.y, v.z, v.w};
#pragma unroll
            for (int e = 0; e < 4; e++) {
                int dim = 4 * cg + e, nt = dim >> 3, nn = dim & 7;
                sVf[((((kt * 2 + nt) << 1) + r) << 5) + nn * 4 + k4] = vv[e];
            }
        }
        __syncthreads();
#pragma unroll 2
        for (int kt = 0; kt < 16; kt++) {
            uint32 vb00 = __float_as_uint(sVf[(((kt * 2 + 0) << 1) + 0) * 32 + lane]);
            uint32 vb01 = __float_as_uint(sVf[(((kt * 2 + 0) << 1) + 1) * 32 + lane]);
            uint32 vb10 = __float_as_uint(sVf[(((kt * 2 + 1) << 1) + 0) * 32 + lane]);
            uint32 vb11 = __float_as_uint(sVf[(((kt * 2 + 1) << 1) + 1) * 32 + lane]);
            int src  = (lane & ~3) | (tg >> 1);
            int src2 = src + 2;
#pragma unroll
            for (int h = 0; h < 4; h++) {
                uint32 kb0 = __float_as_uint(sKf[((kt * 4 + h) * 2 + 0) * 32 + lane]);
                uint32 kb1 = __float_as_uint(sKf[((kt * 4 + h) * 2 + 1) * 32 + lane]);
                float d0 = 0.f, d1 = 0.f, d2 = 0.f, d3 = 0.f;
                MMA_TF32(d0, d1, d2, d3, qa[h][0], qa[h][1], qa[h][2], qa[h][3], kb0, kb1);
                float p0 = ex2f(d0), p1 = ex2f(d1), p2 = ex2f(d2), p3 = ex2f(d3);
                l[h][0] += p0 + p1;
                l[h][1] += p2 + p3;
                float u00 = __shfl_sync(0xffffffffu, p0, src);
                float u01 = __shfl_sync(0xffffffffu, p1, src);
                float u10 = __shfl_sync(0xffffffffu, p2, src);
                float u11 = __shfl_sync(0xffffffffu, p3, src);
                float u20 = __shfl_sync(0xffffffffu, p0, src2);
                float u21 = __shfl_sync(0xffffffffu, p1, src2);
                float u30 = __shfl_sync(0xffffffffu, p2, src2);
                float u31 = __shfl_sync(0xffffffffu, p3, src2);
                bool odd = (tg & 1);
                // raw fp32 bits as tf32 operands: HW reads the tf32 field (truncation);
                // P in (0,1], error <= 2^-11 relative, unbiased across keys.
                uint32 pa0 = __float_as_uint(odd ? u01 : u00);
                uint32 pa1 = __float_as_uint(odd ? u11 : u10);
                uint32 pa2 = __float_as_uint(odd ? u21 : u20);
                uint32 pa3 = __float_as_uint(odd ? u31 : u30);
                MMA_TF32(o[h][0][0], o[h][0][1], o[h][0][2], o[h][0][3],
                         pa0, pa1, pa2, pa3, vb00, vb01);
                MMA_TF32(o[h][1][0], o[h][1][1], o[h][1][2], o[h][1][3],
                         pa0, pa1, pa2, pa3, vb10, vb11);
            }
        }
    }

    // merge partials
#pragma unroll
    for (int h = 0; h < 4; h++) {
        float l0 = l[h][0], l1 = l[h][1];
        l0 += __shfl_xor_sync(0xffffffffu, l0, 1);
        l0 += __shfl_xor_sync(0xffffffffu, l0, 2);
        l1 += __shfl_xor_sync(0xffffffffu, l1, 1);
        l1 += __shfl_xor_sync(0xffffffffu, l1, 2);
        if (tg == 0) {
            atomicAdd(&g_lAcc[(b * N_ + n0w + gID    ) * 4 + h], l0);
            atomicAdd(&g_lAcc[(b * N_ + n0w + gID + 8) * 4 + h], l1);
        }
#pragma unroll
        for (int nt = 0; nt < 2; nt++) {
            float* base0 = g_oAcc + (((size_t)(b * N_ + n0w + gID    )) * 4 + h) * 16 + nt * 8 + tg * 2;
            float* base1 = g_oAcc + (((size_t)(b * N_ + n0w + gID + 8)) * 4 + h) * 16 + nt * 8 + tg * 2;
            atomicAdd(base0 + 0, o[h][nt][0]);
            atomicAdd(base0 + 1, o[h][nt][1]);
            atomicAdd(base1 + 0, o[h][nt][2]);
            atomicAdd(base1 + 1, o[h][nt][3]);
        }
    }
}

// ---------------- kernel 2b: attention epilogue ----------------
__global__ __launch_bounds__(128) void attn_epi(const float* __restrict__ v_gains) {
    int b = blockIdx.y;
    int t = threadIdx.x;
    int n = blockIdx.x * 128 + t;
    __shared__ float sW[4][16];
    float gain = 0.25f * v_gains[0];
    float att[16];
#pragma unroll
    for (int d = 0; d < 16; d++) att[d] = 0.f;
#pragma unroll
    for (int h = 0; h < 4; h++) {
        float inv = rcpf(g_lAcc[(b * N_ + n) * 4 + h]);
        const float4* op = (const float4*)(g_oAcc + (((size_t)(b * N_ + n)) * 4 + h) * 16);
#pragma unroll
        for (int i = 0; i < 4; i++) {
            float4 v = op[i];
            att[4*i]   = fmaf(v.x, inv, att[4*i]);
            att[4*i+1] = fmaf(v.y, inv, att[4*i+1]);
            att[4*i+2] = fmaf(v.z, inv, att[4*i+2]);
            att[4*i+3] = fmaf(v.w, inv, att[4*i+3]);
        }
    }
#pragma unroll
    for (int d = 0; d < 16; d++) att[d] *= gain;
    float4* ap = (float4*)(g_att + ((size_t)b * N_ + n) * 16);
#pragma unroll
    for (int i = 0; i < 4; i++)
        ap[i] = make_float4(att[4*i], att[4*i+1], att[4*i+2], att[4*i+3]);
    float w[16];
#pragma unroll
    for (int d = 0; d < 16; d++) {
        float v = att[d];
        v += __shfl_xor_sync(0xffffffffu, v, 1);
        v += __shfl_xor_sync(0xffffffffu, v, 2);
        v += __shfl_xor_sync(0xffffffffu, v, 4);
        v += __shfl_xor_sync(0xffffffffu, v, 8);
        v += __shfl_xor_sync(0xffffffffu, v, 16);
        w[d] = v;
    }
    if ((t & 31) == 0) {
#pragma unroll
        for (int d = 0; d < 16; d++) sW[t >> 5][d] = w[d];
    }
    __syncthreads();
    if (t < 16) {
        float s = sW[0][t] + sW[1][t] + sW[2][t] + sW[3][t];
        atomicAdd(&g_wsumAcc[b * 16 + t], s);
    }
}

// ---------------- kernel 3: candidates + fim partials ----------------
__global__ __launch_bounds__(256) void cand_kernel(const float* __restrict__ W_act,
                            const float* __restrict__ b_act) {
    int b = blockIdx.z, k = blockIdx.y, ch = blockIdx.x;
    __shared__ __align__(16) float W[16][16];
    __shared__ __align__(16) float bias[16];
    int t = threadIdx.x;
    W[t >> 4][t & 15] = W_act[(k * 16 + (t >> 4)) * 16 + (t & 15)];
    if (t < 16) bias[t] = b_act[k * 16 + t] + g_hypf[(b * K_ + k) * 16 + t];
    __syncthreads();
    int n = ch * 256 + t;
    float a[16];
    const float4* ap = (const float4*)(g_att + ((size_t)b * N_ + n) * 16);
#pragma unroll
    for (int i = 0; i < 4; i++) { float4 v = ap[i]; a[4*i]=v.x; a[4*i+1]=v.y; a[4*i+2]=v.z; a[4*i+3]=v.w; }
    ull ad[16];
#pragma unroll
    for (int d = 0; d < 16; d++) ad[d] = pack2(a[d], a[d]);
    float c[16], ss = 0.f;
#pragma unroll
    for (int e2 = 0; e2 < 8; e2++) {
        ull acc = ((const ull*)bias)[e2];
#pragma unroll
        for (int d = 0; d < 16; d++) FMA2(acc, ad[d], ((const ull*)&W[d][0])[e2], acc);
        float v0, v1; unpack2(acc, v0, v1);
        v0 = fast_tanh(v0); v1 = fast_tanh(v1);
        c[2*e2] = v0; c[2*e2+1] = v1;
        ss = fmaf(v0, v0, fmaf(v1, v1, ss));
    }
    float4* cp = (float4*)(g_cand + (((size_t)(b * K_ + k)) * N_ + n) * 16);
#pragma unroll
    for (int i = 0; i < 4; i++) cp[i] = make_float4(c[4*i], c[4*i+1], c[4*i+2], c[4*i+3]);
    ss *= (1.f / 16.f);
#pragma unroll
    for (int off = 16; off > 0; off >>= 1) ss += __shfl_xor_sync(0xffffffffu, ss, off);
    __shared__ float wsums[8];
    if ((t & 31) == 0) wsums[t >> 5] = ss;
    __syncthreads();
    if (t == 0) {
        float tot = 0.f;
#pragma unroll
        for (int i = 0; i < 8; i++) tot += wsums[i];
        atomicAdd(&g_fimraw[b * K_ + k], tot);
    }
}

// ---------------- kernel 4: fused small-math + weighted select + gates + norm ----------------
__global__ __launch_bounds__(256) void final_kernel(const float* __restrict__ state,
                            const float* __restrict__ hyp, const float* __restrict__ R_accum,
                            const float* __restrict__ W_ws, const float* __restrict__ b_ws,
                            const float* __restrict__ W_s1, const float* __restrict__ b_s1,
                            const float* __restrict__ W_s2, const float* __restrict__ b_s2,
                            const float* __restrict__ W_lift, const float* __restrict__ b_lift,
                            const float* __restrict__ rotors,
                            const float* __restrict__ Wg1, const float* __restrict__ bg1,
                            const float* __restrict__ Wg2, const float* __restrict__ bg2,
                            const float* __restrict__ Wc1, const float* __restrict__ bc1,
                            const float* __restrict__ Wc2, const float* __restrict__ bc2,
                            const float* __restrict__ norm_scale,
                            float* __restrict__ out_ns, float* __restrict__ out_newhyp,
                            float* __restrict__ out_R, float* __restrict__ out_fim,
                            float* __restrict__ out_w, float* __restrict__ out_gate) {
    int b = blockIdx.y;
    int bx = blockIdx.x;
    int t = threadIdx.x;
    int n = bx * 256 + t;

    __shared__ __align__(16) float sWg1[32][64];
    __shared__ __align__(16) float sWg2[64][16];
    __shared__ __align__(16) float sbg1[64], sbg2[16];
    __shared__ float sWc1[2][16], sbc1[16], sWc2[16], sns[16];
    __shared__ float sW1[640], sW2[320];
    __shared__ float sC[256];
    __shared__ float s_nh[8][4], s_logit[8], s_fim[8];
    __shared__ float s_w[8], s_agg[4], s_mod[16];
    __shared__ float s_Rt[16], s_Racc[16], s_Rn[16];
    __shared__ float sbc2, s_g0;

    for (int i = t; i < 2048; i += 256) sWg1[i >> 6][i & 63] = Wg1[i];
    for (int i = t; i < 1024; i += 256) sWg2[i >> 4][i & 15] = Wg2[i];
    for (int i = t; i < 640; i += 256) sW1[i] = W_s1[i];
    for (int i = t; i < 320; i += 256) sW2[i] = W_s2[i];
    if (bx == 0) sC[t] = cayley_sign(t >> 4, t & 15);
    if (t < 64) sbg1[t] = bg1[t];
    if (t < 16) { sbg2[t] = bg2[t]; sbc1[t] = bc1[t]; sWc2[t] = Wc2[t]; sns[t] = norm_scale[t]; }
    if (t < 32) sWc1[t >> 4][t & 15] = Wc1[t];
    if (t == 0) sbc2 = bc2[0];
    __syncthreads();

    const float invN = 1.f / (float)N_;
    if (t < 32) {
        int p = t >> 2;
        int q = t & 3;
        float fim = g_fimraw[b * 8 + p] * invN;
        float feat[10];
#pragma unroll
        for (int c = 0; c < 4; c++) feat[c] = hyp[(b * 8 + p) * 4 + c];
#pragma unroll
        for (int c = 0; c < 4; c++) {
            float v = b_ws[c];
#pragma unroll
            for (int d = 0; d < 16; d++)
                v = fmaf(g_wsumAcc[b * 16 + d] * invN, W_ws[d * 4 + c], v);
            feat[4 + c] = v;
        }
        feat[8] = fim; feat[9] = fim;
        float sp[5] = {0.f, 0.f, 0.f, 0.f, 0.f};
        for (int j = q; j < 64; j += 4) {
            float h = b_s1[j];
#pragma unroll
            for (int i = 0; i < 10; i++) h = fmaf(feat[i], sW1[i * 64 + j], h);
            h = fmaxf(h, 0.f);
#pragma unroll
            for (int c = 0; c < 5; c++) sp[c] = fmaf(h, sW2[j * 5 + c], sp[c]);
        }
#pragma unroll
        for (int c = 0; c < 5; c++) {
            sp[c] += __shfl_xor_sync(0xffffffffu, sp[c], 1);
            sp[c] += __shfl_xor_sync(0xffffffffu, sp[c], 2);
        }
        if (q == 0) {
            s_fim[p] = fim;
#pragma unroll
            for (int c = 0; c < 4; c++) s_nh[p][c] = feat[c] + sp[c] + b_s2[c];
            s_logit[p] = sp[4] + b_s2[4];
        }
        __syncwarp();
        if (t == 0) {
            float mx = -1e30f;
#pragma unroll
            for (int k = 0; k < 8; k++) mx = fmaxf(mx, s_logit[k]);
            float e[8], se = 0.f;
#pragma unroll
            for (int k = 0; k < 8; k++) { e[k] = __expf(s_logit[k] - mx); se += e[k]; }
            float inv = 1.f / se;
            float agg[4] = {0.f, 0.f, 0.f, 0.f};
#pragma unroll
            for (int k = 0; k < 8; k++) {
                float w = e[k] * inv;
                s_w[k] = w;
#pragma unroll
                for (int c = 0; c < 4; c++) agg[c] = fmaf(w, s_nh[k][c], agg[c]);
            }
#pragma unroll
            for (int c = 0; c < 4; c++) s_agg[c] = agg[c];
        }
        __syncwarp();
        if (t < 16) {
            float v = b_lift[t];
#pragma unroll
            for (int c = 0; c < 4; c++) v = fmaf(s_agg[c], W_lift[c * 16 + t], v);
            s_mod[t] = 1.f + tanhf(v);
        }
    }
    __syncthreads();

    if (bx == 0) {
        if (t < 8) { out_fim[b * 8 + t] = s_fim[t]; out_w[b * 8 + t] = s_w[t]; }
        if (t < 32) out_newhyp[b * 32 + t] = s_nh[t >> 2][t & 3];
        if (t < 16) {
            float v = 0.f;
#pragma unroll
            for (int k = 0; k < 8; k++) v = fmaf(s_w[k], rotors[k * 16 + t], v);
            s_Rt[t] = v;
            s_Racc[t] = R_accum[b * 16 + t];
        }
    }
    __syncthreads();
    if (bx == 0 && t < 16) {
        float v = 0.f;
#pragma unroll
        for (int a = 0; a < 16; a++) {
            int bb = a ^ t;
            v = fmaf(sC[a * 16 + bb] * s_Rt[a], s_Racc[bb], v);
        }
        s_Rn[t] = v;
    }
    __syncthreads();
    if (bx == 0 && t == 0) {
        float g0 = 0.f;
#pragma unroll
        for (int a = 0; a < 16; a++)
            g0 += sC[a * 16 + a] * s_Rn[a] * s_Rn[a] * rev_sign(a);
        s_g0 = rsqrtf(fmaxf(fabsf(g0), 1e-6f));
    }
    __syncthreads();
    if (bx == 0 && t < 16) out_R[b * 16 + t] = s_Rn[t] * s_g0;

    float in[32];
    const float4* sp = (const float4*)(state + ((size_t)b * N_ + n) * 16);
#pragma unroll
    for (int i = 0; i < 4; i++) { float4 v = sp[i]; in[4*i]=v.x; in[4*i+1]=v.y; in[4*i+2]=v.z; in[4*i+3]=v.w; }

    float ns_[16];
#pragma unroll
    for (int e = 0; e < 16; e++) ns_[e] = 0.f;
#pragma unroll
    for (int k = 0; k < 8; k++) {
        const float4* cp = (const float4*)(g_cand + (((size_t)(b * K_ + k)) * N_ + n) * 16);
        float wk = s_w[k];
#pragma unroll
        for (int i = 0; i < 4; i++) {
            float4 v = cp[i];
            ns_[4*i]   = fmaf(wk, v.x, ns_[4*i]);
            ns_[4*i+1] = fmaf(wk, v.y, ns_[4*i+1]);
            ns_[4*i+2] = fmaf(wk, v.z, ns_[4*i+2]);
            ns_[4*i+3] = fmaf(wk, v.w, ns_[4*i+3]);
        }
    }
#pragma unroll
    for (int e = 0; e < 16; e++) { ns_[e] *= s_mod[e]; in[16 + e] = ns_[e]; }

    ull accE[8];
#pragma unroll
    for (int e2 = 0; e2 < 8; e2++) accE[e2] = ((const ull*)sbg2)[e2];
#pragma unroll
    for (int half = 0; half < 2; half++) {
        ull accH[16];
#pragma unroll
        for (int j2 = 0; j2 < 16; j2++) accH[j2] = ((const ull*)sbg1)[half * 16 + j2];
#pragma unroll
        for (int i = 0; i < 32; i++) {
            ull ind = pack2(in[i], in[i]);
            const ull* wrow = (const ull*)&sWg1[i][half * 32];
#pragma unroll
            for (int j2 = 0; j2 < 16; j2++) FMA2(accH[j2], ind, wrow[j2], accH[j2]);
        }
#pragma unroll
        for (int j2 = 0; j2 < 16; j2++) {
            float h0, h1; unpack2(accH[j2], h0, h1);
            h0 = fmaxf(h0, 0.f); h1 = fmaxf(h1, 0.f);
            int j = half * 32 + j2 * 2;
            ull hd0 = pack2(h0, h0), hd1 = pack2(h1, h1);
            const ull* w0 = (const ull*)&sWg2[j][0];
            const ull* w1 = (const ull*)&sWg2[j + 1][0];
#pragma unroll
            for (int e2 = 0; e2 < 8; e2++) {
                FMA2(accE[e2], hd0, w0[e2], accE[e2]);
                FMA2(accE[e2], hd1, w1[e2], accE[e2]);
            }
        }
    }
    float gate[16];
#pragma unroll
    for (int e2 = 0; e2 < 8; e2++) {
        float a0, a1; unpack2(accE[e2], a0, a1);
        gate[2*e2]   = rcpf(1.f + ex2f(-LOG2E_ * a0));
        gate[2*e2+1] = rcpf(1.f + ex2f(-LOG2E_ * a1));
    }

    float cg = sbc2;
#pragma unroll
    for (int j = 0; j < 16; j++) {
        float h = fmaf(in[0], sWc1[0][j], fmaf(ns_[0], sWc1[1][j], sbc1[j]));
        h = fmaxf(h, 0.f);
        cg = fmaf(h, sWc2[j], cg);
    }
    cg = rcpf(1.f + ex2f(-LOG2E_ * cg));

    float val[16];
    val[0] = cg * ns_[0] + (1.f - cg) * in[0];
#pragma unroll
    for (int d = 1; d < 16; d++) val[d] = gate[d] * ns_[d] + (1.f - gate[d]) * in[d];

    float ms = 0.f;
#pragma unroll
    for (int d = 0; d < 16; d++) ms = fmaf(val[d], val[d], ms);
    float r = rsqrtf(ms * (1.f / 16.f) + 1e-6f);

    float4* no = (float4*)(out_ns + ((size_t)b * N_ + n) * 16);
    float4* go = (float4*)(out_gate + ((size_t)b * N_ + n) * 16);
#pragma unroll
    for (int i = 0; i < 4; i++) {
        no[i] = make_float4(val[4*i] * sns[4*i] * r, val[4*i+1] * sns[4*i+1] * r,
                            val[4*i+2] * sns[4*i+2] * r, val[4*i+3] * sns[4*i+3] * r);
        go[i] = make_float4(gate[4*i], gate[4*i+1], gate[4*i+2], gate[4*i+3]);
    }
}

// ---------------- launch ----------------
extern "C" void kernel_launch(void* const* d_in, const int* in_sizes, int n_in,
                              void* d_out, int out_size) {
    const float* state   = (const float*)d_in[0];
    const float* hyp     = (const float*)d_in[1];
    const float* R_accum = (const float*)d_in[2];
    const float* Wq = (const float*)d_in[4];
    const float* bq = (const float*)d_in[5];
    const float* Wk = (const float*)d_in[6];
    const float* bk = (const float*)d_in[7];
    const float* v_gains = (const float*)d_in[8];
    const float* W_act = (const float*)d_in[9];
    const float* b_act = (const float*)d_in[10];
    const float* W_hyp = (const float*)d_in[11];
    const float* b_hyp = (const float*)d_in[12];
    const float* W_ws = (const float*)d_in[13];
    const float* b_ws = (const float*)d_in[14];
    const float* W_s1 = (const float*)d_in[15];
    const float* b_s1 = (const float*)d_in[16];
    const float* W_s2 = (const float*)d_in[17];
    const float* b_s2 = (const float*)d_in[18];
    const float* W_lift = (const float*)d_in[19];
    const float* b_lift = (const float*)d_in[20];
    const float* Wg1 = (const float*)d_in[21];
    const float* bg1 = (const float*)d_in[22];
    const float* Wg2 = (const float*)d_in[23];
    const float* bg2 = (const float*)d_in[24];
    const float* Wc1 = (const float*)d_in[25];
    const float* bc1 = (const float*)d_in[26];
    const float* Wc2 = (const float*)d_in[27];
    const float* bc2 = (const float*)d_in[28];
    const float* norm_scale = (const float*)d_in[29];
    const float* rotors = (const float*)d_in[30];

    float* out = (float*)d_out;
    float* out_ns     = out;
    float* out_newhyp = out + (size_t)B_ * N_ * D_;
    float* out_R      = out_newhyp + B_ * K_ * 4;
    float* out_fim    = out_R + B_ * 16;
    float* out_w      = out_fim + B_ * K_;
    float* out_gate   = out_w + B_ * K_;

    proj_kernel<<<(B_ * N_ * 2) / 128, 128>>>(state, Wq, bq, Wk, bk, hyp, W_hyp, b_hyp);
    attn_kernel<<<dim3(N_ / 128, B_, MSPLIT_), 256>>>();
    attn_epi<<<dim3(N_ / 128, B_), 128>>>(v_gains);
    cand_kernel<<<dim3(N_ / 256, K_, B_), 256>>>(W_act, b_act);
    final_kernel<<<dim3(N_ / 256, B_), 256>>>(state, hyp, R_accum, W_ws, b_ws,
                                              W_s1, b_s1, W_s2, b_s2, W_lift, b_lift, rotors,
                                              Wg1, bg1, Wg2, bg2, Wc1, bc1, Wc2, bc2, norm_scale,
                                              out_ns, out_newhyp, out_R, out_fim, out_w, out_gate);
}

// round 17
// speedup vs baseline: 1.1058x; 1.0175x over previous
#include <cuda_runtime.h>
#include <math.h>

// ---------------- problem constants ----------------
#define B_  8
#define N_  2048
#define D_  16
#define K_  8
#define SCALE_ 0.35355339059327373f     // hd^-0.5
#define LOG2E_ 1.4426950408889634f
#define MSPLIT_ 8

typedef unsigned long long ull;
typedef unsigned int uint32;

// ---------------- packed f32x2 helpers ----------------
#define FMA2(d, a, b, c) asm("fma.rn.f32x2 %0, %1, %2, %3;" : "=l"(d) : "l"(a), "l"(b), "l"(c))
__device__ __forceinline__ ull pack2(float lo, float hi) {
    ull r; asm("mov.b64 %0, {%1, %2};" : "=l"(r) : "f"(lo), "f"(hi)); return r;
}
__device__ __forceinline__ void unpack2(ull v, float& lo, float& hi) {
    asm("mov.b64 {%0, %1}, %2;" : "=f"(lo), "=f"(hi) : "l"(v));
}
__device__ __forceinline__ float ex2f(float x) {
    float r; asm("ex2.approx.f32 %0, %1;" : "=f"(r) : "f"(x)); return r;
}
__device__ __forceinline__ float rcpf(float x) {
    float r; asm("rcp.approx.f32 %0, %1;" : "=f"(r) : "f"(x)); return r;
}
__device__ __forceinline__ float fast_tanh(float x) {
    float e = ex2f(2.8853900817779268f * x);
    return fmaf(-2.f, rcpf(e + 1.f), 1.f);
}
__device__ __forceinline__ uint32 cvt_tf32(float x) {
    uint32 r; asm("cvt.rna.tf32.f32 %0, %1;" : "=r"(r) : "f"(x)); return r;
}
#define MMA_TF32(d0,d1,d2,d3,a0,a1,a2,a3,b0,b1) \
    asm volatile("mma.sync.aligned.m16n8k8.row.col.f32.tf32.tf32.f32 " \
        "{%0,%1,%2,%3},{%4,%5,%6,%7},{%8,%9},{%0,%1,%2,%3};" \
        : "+f"(d0),"+f"(d1),"+f"(d2),"+f"(d3) \
        : "r"(a0),"r"(a1),"r"(a2),"r"(a3),"r"(b0),"r"(b1))
#define REDV2(addr, x, y) \
    asm volatile("red.global.add.v2.f32 [%0], {%1,%2};" :: "l"(addr), "f"(x), "f"(y) : "memory")

// ---------------- scratch ----------------
__device__ float g_Q   [B_ * N_ * 32];   // tf32-rounded, pre-scaled by SCALE*LOG2E
__device__ float g_Kt  [B_ * N_ * 32];   // tf32-rounded
__device__ float g_Vt  [B_ * N_ * 16];   // tf32-rounded state
__device__ float g_att [B_ * N_ * D_];
__device__ float g_cand[(size_t)B_ * K_ * N_ * D_];
__device__ float g_oAcc[(size_t)B_ * N_ * 4 * 16];
__device__ float g_lAcc[B_ * N_ * 4];
__device__ float g_wsumAcc[B_ * D_];
__device__ float g_hypf[B_ * K_ * D_];
__device__ float g_fimraw[B_ * K_];

// ---------------- Cl(3,0,1) helpers ----------------
__device__ __forceinline__ float cayley_sign(int a, int b) {
    int neg = 0;
#pragma unroll
    for (int i = 0; i < 4; i++)
        if ((b >> i) & 1) neg ^= (__popc(a >> (i + 1)) & 1);
    if ((a & b) & 8) return 0.f;
    return neg ? -1.f : 1.f;
}
__device__ __forceinline__ float rev_sign(int i) {
    int p = __popc(i);
    return ((p * (p - 1) / 2) & 1) ? -1.f : 1.f;
}

// ---------------- kernel 1: Q/K/V projection (4 threads/row) + init ----------------
__global__ __launch_bounds__(128) void proj_kernel(const float* __restrict__ state,
                            const float* __restrict__ Wq, const float* __restrict__ bq,
                            const float* __restrict__ Wk, const float* __restrict__ bk,
                            const float* __restrict__ hyp,
                            const float* __restrict__ W_hyp,
                            const float* __restrict__ b_hyp) {
    __shared__ __align__(16) float sW[2][16][32], sb[2][32];
    int t = threadIdx.x;
    int gid = blockIdx.x * 128 + t;           // 0..65535
    int row = gid >> 2;                       // 0..16383
    int part = gid & 3;
    int half = part >> 1;                     // 0 = Q, 1 = K
    int qtr  = part & 1;                      // which 8 outputs
    if (part == 0) {
        float4 z = make_float4(0.f, 0.f, 0.f, 0.f);
        float4* oz = (float4*)g_oAcc;
#pragma unroll
        for (int i = 0; i < 16; i++) oz[row + i * 16384] = z;
        ((float4*)g_lAcc)[row] = z;
    }
    if (blockIdx.x == 0) {
        if (t < B_ * K_) g_fimraw[t] = 0.f;
        if (t < B_ * D_) g_wsumAcc[t] = 0.f;
        for (int i = t; i < B_ * K_ * D_; i += 128) {
            int bk_ = i >> 4, d = i & 15;
            float v = b_hyp[d];
#pragma unroll
            for (int c = 0; c < 4; c++) v = fmaf(hyp[bk_ * 4 + c], W_hyp[c * D_ + d], v);
            g_hypf[i] = v;
        }
    }
    for (int i = t; i < 512; i += 128) {
        sW[0][i >> 5][i & 31] = Wq[i];
        sW[1][i >> 5][i & 31] = Wk[i];
    }
    if (t < 32) { sb[0][t] = bq[t]; sb[1][t] = bk[t]; }
    __syncthreads();

    float s[16];
    const float4* sp = (const float4*)(state + (size_t)row * 16);
#pragma unroll
    for (int i = 0; i < 4; i++) { float4 v = sp[i]; s[4*i]=v.x; s[4*i+1]=v.y; s[4*i+2]=v.z; s[4*i+3]=v.w; }
    ull sd[16];
#pragma unroll
    for (int d = 0; d < 16; d++) sd[d] = pack2(s[d], s[d]);
    const float (*W)[32] = sW[half];
    const float* bb = sb[half];
    const float qs = SCALE_ * LOG2E_;
    float* outbase = half ? g_Kt : g_Q;
    float* qo = outbase + (size_t)row * 32;
#pragma unroll
    for (int c2i = 0; c2i < 8; c2i++) {
        int c2 = qtr * 8 + c2i;
        ull a = ((const ull*)bb)[c2];
#pragma unroll
        for (int d = 0; d < 16; d++)
            FMA2(a, sd[d], ((const ull*)&W[d][0])[c2], a);
        float v0, v1; unpack2(a, v0, v1);
        if (half == 0) { v0 *= qs; v1 *= qs; }
        qo[2*c2]   = __uint_as_float(cvt_tf32(v0));
        qo[2*c2+1] = __uint_as_float(cvt_tf32(v1));
    }
    if (part == 3) {
        float* vt = g_Vt + (size_t)row * 16;
#pragma unroll
        for (int d = 0; d < 16; d++) vt[d] = __uint_as_float(cvt_tf32(s[d]));
    }
}

// ---------------- kernel 2: attention via tf32 warp MMA, m-split 8, v2-red merge ----------------
__global__ __launch_bounds__(256) void attn_kernel() {
    int b    = blockIdx.y;
    int t    = threadIdx.x;
    int w    = t >> 5;
    int lane = t & 31;
    int gID  = lane >> 2;
    int tg   = lane & 3;
    int n0w  = blockIdx.x * 128 + w * 16;
    int mbase = blockIdx.z * 256;

    __shared__ __align__(16) float sKf[16 * 256];
    __shared__ __align__(16) float sVf[16 * 128];

    uint32 qa[4][4];
    {
        const float* Qb = g_Q + ((size_t)b * N_ + n0w) * 32;
#pragma unroll
        for (int h = 0; h < 4; h++) {
            qa[h][0] = __float_as_uint(Qb[(gID    ) * 32 + h * 8 + tg    ]);
            qa[h][1] = __float_as_uint(Qb[(gID + 8) * 32 + h * 8 + tg    ]);
            qa[h][2] = __float_as_uint(Qb[(gID    ) * 32 + h * 8 + tg + 4]);
            qa[h][3] = __float_as_uint(Qb[(gID + 8) * 32 + h * 8 + tg + 4]);
        }
    }
    float o[4][2][4];
#pragma unroll
    for (int h = 0; h < 4; h++)
#pragma unroll
        for (int nt = 0; nt < 2; nt++)
#pragma unroll
            for (int r = 0; r < 4; r++) o[h][nt][r] = 0.f;
    float l[4][2];
#pragma unroll
    for (int h = 0; h < 4; h++) { l[h][0] = 0.f; l[h][1] = 0.f; }

#pragma unroll
    for (int mt = 0; mt < 2; mt++) {
        int m0 = mbase + mt * 128;
        __syncthreads();
#pragma unroll
        for (int i = 0; i < 4; i++) {
            int idx = t + i * 256;
            int key = idx >> 3, c = idx & 7;
            float4 v = ((const float4*)(g_Kt + ((size_t)b * N_ + m0 + key) * 32))[c];
            int kt = key >> 3, k8 = key & 7;
            float vv[4] = {v.x, v.y, v.z, v.w};
#pragma unroll
            for (int e = 0; e < 4; e++) {
                int col = 4 * c + e, h = col >> 3, j = col & 7, r = j >> 2, jm = j & 3;
                sKf[(((kt * 4 + h) * 2 + r) << 5) + k8 * 4 + jm] = vv[e];
            }
        }
#pragma unroll
        for (int i = 0; i < 2; i++) {
            int idx = t + i * 256;
            int key = idx >> 2, cg = idx & 3;
            float4 v = ((const float4*)(g_Vt + ((size_t)b * N_ + m0 + key) * 16))[cg];
            int kt = key >> 3, k8 = key & 7, r = k8 >> 2, k4 = k8 & 3;
            float vv[4] = {v.x, v.y, v.z, v.w};
#pragma unroll
            for (int e = 0; e < 4; e++) {
                int dim = 4 * cg + e, nt = dim >> 3, nn = dim & 7;
                sVf[((((kt * 2 + nt) << 1) + r) << 5) + nn * 4 + k4] = vv[e];
            }
        }
        __syncthreads();
#pragma unroll 2
        for (int kt = 0; kt < 16; kt++) {
            uint32 vb00 = __float_as_uint(sVf[(((kt * 2 + 0) << 1) + 0) * 32 + lane]);
            uint32 vb01 = __float_as_uint(sVf[(((kt * 2 + 0) << 1) + 1) * 32 + lane]);
            uint32 vb10 = __float_as_uint(sVf[(((kt * 2 + 1) << 1) + 0) * 32 + lane]);
            uint32 vb11 = __float_as_uint(sVf[(((kt * 2 + 1) << 1) + 1) * 32 + lane]);
            int src  = (lane & ~3) | (tg >> 1);
            int src2 = src + 2;
#pragma unroll
            for (int h = 0; h < 4; h++) {
                uint32 kb0 = __float_as_uint(sKf[((kt * 4 + h) * 2 + 0) * 32 + lane]);
                uint32 kb1 = __float_as_uint(sKf[((kt * 4 + h) * 2 + 1) * 32 + lane]);
                float d0 = 0.f, d1 = 0.f, d2 = 0.f, d3 = 0.f;
                MMA_TF32(d0, d1, d2, d3, qa[h][0], qa[h][1], qa[h][2], qa[h][3], kb0, kb1);
                float p0 = ex2f(d0), p1 = ex2f(d1), p2 = ex2f(d2), p3 = ex2f(d3);
                l[h][0] += p0 + p1;
                l[h][1] += p2 + p3;
                float u00 = __shfl_sync(0xffffffffu, p0, src);
                float u01 = __shfl_sync(0xffffffffu, p1, src);
                float u10 = __shfl_sync(0xffffffffu, p2, src);
                float u11 = __shfl_sync(0xffffffffu, p3, src);
                float u20 = __shfl_sync(0xffffffffu, p0, src2);
                float u21 = __shfl_sync(0xffffffffu, p1, src2);
                float u30 = __shfl_sync(0xffffffffu, p2, src2);
                float u31 = __shfl_sync(0xffffffffu, p3, src2);
                bool odd = (tg & 1);
                uint32 pa0 = __float_as_uint(odd ? u01 : u00);
                uint32 pa1 = __float_as_uint(odd ? u11 : u10);
                uint32 pa2 = __float_as_uint(odd ? u21 : u20);
                uint32 pa3 = __float_as_uint(odd ? u31 : u30);
                MMA_TF32(o[h][0][0], o[h][0][1], o[h][0][2], o[h][0][3],
                         pa0, pa1, pa2, pa3, vb00, vb01);
                MMA_TF32(o[h][1][0], o[h][1][1], o[h][1][2], o[h][1][3],
                         pa0, pa1, pa2, pa3, vb10, vb11);
            }
        }
    }

    // merge partials (l: shuffle + scalar atomic; O: v2 vector reductions)
#pragma unroll
    for (int h = 0; h < 4; h++) {
        float l0 = l[h][0], l1 = l[h][1];
        l0 += __shfl_xor_sync(0xffffffffu, l0, 1);
        l0 += __shfl_xor_sync(0xffffffffu, l0, 2);
        l1 += __shfl_xor_sync(0xffffffffu, l1, 1);
        l1 += __shfl_xor_sync(0xffffffffu, l1, 2);
        if (tg == 0) {
            atomicAdd(&g_lAcc[(b * N_ + n0w + gID    ) * 4 + h], l0);
            atomicAdd(&g_lAcc[(b * N_ + n0w + gID + 8) * 4 + h], l1);
        }
#pragma unroll
        for (int nt = 0; nt < 2; nt++) {
            float* base0 = g_oAcc + (((size_t)(b * N_ + n0w + gID    )) * 4 + h) * 16 + nt * 8 + tg * 2;
            float* base1 = g_oAcc + (((size_t)(b * N_ + n0w + gID + 8)) * 4 + h) * 16 + nt * 8 + tg * 2;
            REDV2(base0, o[h][nt][0], o[h][nt][1]);
            REDV2(base1, o[h][nt][2], o[h][nt][3]);
        }
    }
}

// ---------------- kernel 2b: attention epilogue ----------------
__global__ __launch_bounds__(128) void attn_epi(const float* __restrict__ v_gains) {
    int b = blockIdx.y;
    int t = threadIdx.x;
    int n = blockIdx.x * 128 + t;
    __shared__ float sW[4][16];
    float gain = 0.25f * v_gains[0];
    float att[16];
#pragma unroll
    for (int d = 0; d < 16; d++) att[d] = 0.f;
#pragma unroll
    for (int h = 0; h < 4; h++) {
        float inv = rcpf(g_lAcc[(b * N_ + n) * 4 + h]);
        const float4* op = (const float4*)(g_oAcc + (((size_t)(b * N_ + n)) * 4 + h) * 16);
#pragma unroll
        for (int i = 0; i < 4; i++) {
            float4 v = op[i];
            att[4*i]   = fmaf(v.x, inv, att[4*i]);
            att[4*i+1] = fmaf(v.y, inv, att[4*i+1]);
            att[4*i+2] = fmaf(v.z, inv, att[4*i+2]);
            att[4*i+3] = fmaf(v.w, inv, att[4*i+3]);
        }
    }
#pragma unroll
    for (int d = 0; d < 16; d++) att[d] *= gain;
    float4* ap = (float4*)(g_att + ((size_t)b * N_ + n) * 16);
#pragma unroll
    for (int i = 0; i < 4; i++)
        ap[i] = make_float4(att[4*i], att[4*i+1], att[4*i+2], att[4*i+3]);
    float w[16];
#pragma unroll
    for (int d = 0; d < 16; d++) {
        float v = att[d];
        v += __shfl_xor_sync(0xffffffffu, v, 1);
        v += __shfl_xor_sync(0xffffffffu, v, 2);
        v += __shfl_xor_sync(0xffffffffu, v, 4);
        v += __shfl_xor_sync(0xffffffffu, v, 8);
        v += __shfl_xor_sync(0xffffffffu, v, 16);
        w[d] = v;
    }
    if ((t & 31) == 0) {
#pragma unroll
        for (int d = 0; d < 16; d++) sW[t >> 5][d] = w[d];
    }
    __syncthreads();
    if (t < 16) {
        float s = sW[0][t] + sW[1][t] + sW[2][t] + sW[3][t];
        atomicAdd(&g_wsumAcc[b * 16 + t], s);
    }
}

// ---------------- kernel 3: candidates + fim partials ----------------
__global__ __launch_bounds__(256) void cand_kernel(const float* __restrict__ W_act,
                            const float* __restrict__ b_act) {
    int b = blockIdx.z, k = blockIdx.y, ch = blockIdx.x;
    __shared__ __align__(16) float W[16][16];
    __shared__ __align__(16) float bias[16];
    int t = threadIdx.x;
    W[t >> 4][t & 15] = W_act[(k * 16 + (t >> 4)) * 16 + (t & 15)];
    if (t < 16) bias[t] = b_act[k * 16 + t] + g_hypf[(b * K_ + k) * 16 + t];
    __syncthreads();
    int n = ch * 256 + t;
    float a[16];
    const float4* ap = (const float4*)(g_att + ((size_t)b * N_ + n) * 16);
#pragma unroll
    for (int i = 0; i < 4; i++) { float4 v = ap[i]; a[4*i]=v.x; a[4*i+1]=v.y; a[4*i+2]=v.z; a[4*i+3]=v.w; }
    ull ad[16];
#pragma unroll
    for (int d = 0; d < 16; d++) ad[d] = pack2(a[d], a[d]);
    float c[16], ss = 0.f;
#pragma unroll
    for (int e2 = 0; e2 < 8; e2++) {
        ull acc = ((const ull*)bias)[e2];
#pragma unroll
        for (int d = 0; d < 16; d++) FMA2(acc, ad[d], ((const ull*)&W[d][0])[e2], acc);
        float v0, v1; unpack2(acc, v0, v1);
        v0 = fast_tanh(v0); v1 = fast_tanh(v1);
        c[2*e2] = v0; c[2*e2+1] = v1;
        ss = fmaf(v0, v0, fmaf(v1, v1, ss));
    }
    float4* cp = (float4*)(g_cand + (((size_t)(b * K_ + k)) * N_ + n) * 16);
#pragma unroll
    for (int i = 0; i < 4; i++) cp[i] = make_float4(c[4*i], c[4*i+1], c[4*i+2], c[4*i+3]);
    ss *= (1.f / 16.f);
#pragma unroll
    for (int off = 16; off > 0; off >>= 1) ss += __shfl_xor_sync(0xffffffffu, ss, off);
    __shared__ float wsums[8];
    if ((t & 31) == 0) wsums[t >> 5] = ss;
    __syncthreads();
    if (t == 0) {
        float tot = 0.f;
#pragma unroll
        for (int i = 0; i < 8; i++) tot += wsums[i];
        atomicAdd(&g_fimraw[b * K_ + k], tot);
    }
}

// ---------------- kernel 4: fused small-math + weighted select + gates + norm ----------------
__global__ __launch_bounds__(256) void final_kernel(const float* __restrict__ state,
                            const float* __restrict__ hyp, const float* __restrict__ R_accum,
                            const float* __restrict__ W_ws, const float* __restrict__ b_ws,
                            const float* __restrict__ W_s1, const float* __restrict__ b_s1,
                            const float* __restrict__ W_s2, const float* __restrict__ b_s2,
                            const float* __restrict__ W_lift, const float* __restrict__ b_lift,
                            const float* __restrict__ rotors,
                            const float* __restrict__ Wg1, const float* __restrict__ bg1,
                            const float* __restrict__ Wg2, const float* __restrict__ bg2,
                            const float* __restrict__ Wc1, const float* __restrict__ bc1,
                            const float* __restrict__ Wc2, const float* __restrict__ bc2,
                            const float* __restrict__ norm_scale,
                            float* __restrict__ out_ns, float* __restrict__ out_newhyp,
                            float* __restrict__ out_R, float* __restrict__ out_fim,
                            float* __restrict__ out_w, float* __restrict__ out_gate) {
    int b = blockIdx.y;
    int bx = blockIdx.x;
    int t = threadIdx.x;
    int n = bx * 256 + t;

    __shared__ __align__(16) float sWg1[32][64];
    __shared__ __align__(16) float sWg2[64][16];
    __shared__ __align__(16) float sbg1[64], sbg2[16];
    __shared__ float sWc1[2][16], sbc1[16], sWc2[16], sns[16];
    __shared__ float sW1[640], sW2[320];
    __shared__ float sC[256];
    __shared__ float s_nh[8][4], s_logit[8], s_fim[8];
    __shared__ float s_w[8], s_agg[4], s_mod[16];
    __shared__ float s_Rt[16], s_Racc[16], s_Rn[16];
    __shared__ float sbc2, s_g0;

    for (int i = t; i < 2048; i += 256) sWg1[i >> 6][i & 63] = Wg1[i];
    for (int i = t; i < 1024; i += 256) sWg2[i >> 4][i & 15] = Wg2[i];
    for (int i = t; i < 640; i += 256) sW1[i] = W_s1[i];
    for (int i = t; i < 320; i += 256) sW2[i] = W_s2[i];
    if (bx == 0) sC[t] = cayley_sign(t >> 4, t & 15);
    if (t < 64) sbg1[t] = bg1[t];
    if (t < 16) { sbg2[t] = bg2[t]; sbc1[t] = bc1[t]; sWc2[t] = Wc2[t]; sns[t] = norm_scale[t]; }
    if (t < 32) sWc1[t >> 4][t & 15] = Wc1[t];
    if (t == 0) sbc2 = bc2[0];
    __syncthreads();

    const float invN = 1.f / (float)N_;
    if (t < 32) {
        int p = t >> 2;
        int q = t & 3;
        float fim = g_fimraw[b * 8 + p] * invN;
        float feat[10];
#pragma unroll
        for (int c = 0; c < 4; c++) feat[c] = hyp[(b * 8 + p) * 4 + c];
#pragma unroll
        for (int c = 0; c < 4; c++) {
            float v = b_ws[c];
#pragma unroll
            for (int d = 0; d < 16; d++)
                v = fmaf(g_wsumAcc[b * 16 + d] * invN, W_ws[d * 4 + c], v);
            feat[4 + c] = v;
        }
        feat[8] = fim; feat[9] = fim;
        float sp[5] = {0.f, 0.f, 0.f, 0.f, 0.f};
        for (int j = q; j < 64; j += 4) {
            float h = b_s1[j];
#pragma unroll
            for (int i = 0; i < 10; i++) h = fmaf(feat[i], sW1[i * 64 + j], h);
            h = fmaxf(h, 0.f);
#pragma unroll
            for (int c = 0; c < 5; c++) sp[c] = fmaf(h, sW2[j * 5 + c], sp[c]);
        }
#pragma unroll
        for (int c = 0; c < 5; c++) {
            sp[c] += __shfl_xor_sync(0xffffffffu, sp[c], 1);
            sp[c] += __shfl_xor_sync(0xffffffffu, sp[c], 2);
        }
        if (q == 0) {
            s_fim[p] = fim;
#pragma unroll
            for (int c = 0; c < 4; c++) s_nh[p][c] = feat[c] + sp[c] + b_s2[c];
            s_logit[p] = sp[4] + b_s2[4];
        }
        __syncwarp();
        if (t == 0) {
            float mx = -1e30f;
#pragma unroll
            for (int k = 0; k < 8; k++) mx = fmaxf(mx, s_logit[k]);
            float e[8], se = 0.f;
#pragma unroll
            for (int k = 0; k < 8; k++) { e[k] = __expf(s_logit[k] - mx); se += e[k]; }
            float inv = 1.f / se;
            float agg[4] = {0.f, 0.f, 0.f, 0.f};
#pragma unroll
            for (int k = 0; k < 8; k++) {
                float w = e[k] * inv;
                s_w[k] = w;
#pragma unroll
                for (int c = 0; c < 4; c++) agg[c] = fmaf(w, s_nh[k][c], agg[c]);
            }
#pragma unroll
            for (int c = 0; c < 4; c++) s_agg[c] = agg[c];
        }
        __syncwarp();
        if (t < 16) {
            float v = b_lift[t];
#pragma unroll
            for (int c = 0; c < 4; c++) v = fmaf(s_agg[c], W_lift[c * 16 + t], v);
            s_mod[t] = 1.f + tanhf(v);
        }
    }
    __syncthreads();

    if (bx == 0) {
        if (t < 8) { out_fim[b * 8 + t] = s_fim[t]; out_w[b * 8 + t] = s_w[t]; }
        if (t < 32) out_newhyp[b * 32 + t] = s_nh[t >> 2][t & 3];
        if (t < 16) {
            float v = 0.f;
#pragma unroll
            for (int k = 0; k < 8; k++) v = fmaf(s_w[k], rotors[k * 16 + t], v);
            s_Rt[t] = v;
            s_Racc[t] = R_accum[b * 16 + t];
        }
    }
    __syncthreads();
    if (bx == 0 && t < 16) {
        float v = 0.f;
#pragma unroll
        for (int a = 0; a < 16; a++) {
            int bb = a ^ t;
            v = fmaf(sC[a * 16 + bb] * s_Rt[a], s_Racc[bb], v);
        }
        s_Rn[t] = v;
    }
    __syncthreads();
    if (bx == 0 && t == 0) {
        float g0 = 0.f;
#pragma unroll
        for (int a = 0; a < 16; a++)
            g0 += sC[a * 16 + a] * s_Rn[a] * s_Rn[a] * rev_sign(a);
        s_g0 = rsqrtf(fmaxf(fabsf(g0), 1e-6f));
    }
    __syncthreads();
    if (bx == 0 && t < 16) out_R[b * 16 + t] = s_Rn[t] * s_g0;

    float in[32];
    const float4* sp = (const float4*)(state + ((size_t)b * N_ + n) * 16);
#pragma unroll
    for (int i = 0; i < 4; i++) { float4 v = sp[i]; in[4*i]=v.x; in[4*i+1]=v.y; in[4*i+2]=v.z; in[4*i+3]=v.w; }

    float ns_[16];
#pragma unroll
    for (int e = 0; e < 16; e++) ns_[e] = 0.f;
#pragma unroll
    for (int k = 0; k < 8; k++) {
        const float4* cp = (const float4*)(g_cand + (((size_t)(b * K_ + k)) * N_ + n) * 16);
        float wk = s_w[k];
#pragma unroll
        for (int i = 0; i < 4; i++) {
            float4 v = cp[i];
            ns_[4*i]   = fmaf(wk, v.x, ns_[4*i]);
            ns_[4*i+1] = fmaf(wk, v.y, ns_[4*i+1]);
            ns_[4*i+2] = fmaf(wk, v.z, ns_[4*i+2]);
            ns_[4*i+3] = fmaf(wk, v.w, ns_[4*i+3]);
        }
    }
#pragma unroll
    for (int e = 0; e < 16; e++) { ns_[e] *= s_mod[e]; in[16 + e] = ns_[e]; }

    ull accE[8];
#pragma unroll
    for (int e2 = 0; e2 < 8; e2++) accE[e2] = ((const ull*)sbg2)[e2];
#pragma unroll
    for (int half = 0; half < 2; half++) {
        ull accH[16];
#pragma unroll
        for (int j2 = 0; j2 < 16; j2++) accH[j2] = ((const ull*)sbg1)[half * 16 + j2];
#pragma unroll
        for (int i = 0; i < 32; i++) {
            ull ind = pack2(in[i], in[i]);
            const ull* wrow = (const ull*)&sWg1[i][half * 32];
#pragma unroll
            for (int j2 = 0; j2 < 16; j2++) FMA2(accH[j2], ind, wrow[j2], accH[j2]);
        }
#pragma unroll
        for (int j2 = 0; j2 < 16; j2++) {
            float h0, h1; unpack2(accH[j2], h0, h1);
            h0 = fmaxf(h0, 0.f); h1 = fmaxf(h1, 0.f);
            int j = half * 32 + j2 * 2;
            ull hd0 = pack2(h0, h0), hd1 = pack2(h1, h1);
            const ull* w0 = (const ull*)&sWg2[j][0];
            const ull* w1 = (const ull*)&sWg2[j + 1][0];
#pragma unroll
            for (int e2 = 0; e2 < 8; e2++) {
                FMA2(accE[e2], hd0, w0[e2], accE[e2]);
                FMA2(accE[e2], hd1, w1[e2], accE[e2]);
            }
        }
    }
    float gate[16];
#pragma unroll
    for (int e2 = 0; e2 < 8; e2++) {
        float a0, a1; unpack2(accE[e2], a0, a1);
        gate[2*e2]   = rcpf(1.f + ex2f(-LOG2E_ * a0));
        gate[2*e2+1] = rcpf(1.f + ex2f(-LOG2E_ * a1));
    }

    float cg = sbc2;
#pragma unroll
    for (int j = 0; j < 16; j++) {
        float h = fmaf(in[0], sWc1[0][j], fmaf(ns_[0], sWc1[1][j], sbc1[j]));
        h = fmaxf(h, 0.f);
        cg = fmaf(h, sWc2[j], cg);
    }
    cg = rcpf(1.f + ex2f(-LOG2E_ * cg));

    float val[16];
    val[0] = cg * ns_[0] + (1.f - cg) * in[0];
#pragma unroll
    for (int d = 1; d < 16; d++) val[d] = gate[d] * ns_[d] + (1.f - gate[d]) * in[d];

    float ms = 0.f;
#pragma unroll
    for (int d = 0; d < 16; d++) ms = fmaf(val[d], val[d], ms);
    float r = rsqrtf(ms * (1.f / 16.f) + 1e-6f);

    float4* no = (float4*)(out_ns + ((size_t)b * N_ + n) * 16);
    float4* go = (float4*)(out_gate + ((size_t)b * N_ + n) * 16);
#pragma unroll
    for (int i = 0; i < 4; i++) {
        no[i] = make_float4(val[4*i] * sns[4*i] * r, val[4*i+1] * sns[4*i+1] * r,
                            val[4*i+2] * sns[4*i+2] * r, val[4*i+3] * sns[4*i+3] * r);
        go[i] = make_float4(gate[4*i], gate[4*i+1], gate[4*i+2], gate[4*i+3]);
    }
}

// ---------------- launch ----------------
extern "C" void kernel_launch(void* const* d_in, const int* in_sizes, int n_in,
                              void* d_out, int out_size) {
    const float* state   = (const float*)d_in[0];
    const float* hyp     = (const float*)d_in[1];
    const float* R_accum = (const float*)d_in[2];
    const float* Wq = (const float*)d_in[4];
    const float* bq = (const float*)d_in[5];
    const float* Wk = (const float*)d_in[6];
    const float* bk = (const float*)d_in[7];
    const float* v_gains = (const float*)d_in[8];
    const float* W_act = (const float*)d_in[9];
    const float* b_act = (const float*)d_in[10];
    const float* W_hyp = (const float*)d_in[11];
    const float* b_hyp = (const float*)d_in[12];
    const float* W_ws = (const float*)d_in[13];
    const float* b_ws = (const float*)d_in[14];
    const float* W_s1 = (const float*)d_in[15];
    const float* b_s1 = (const float*)d_in[16];
    const float* W_s2 = (const float*)d_in[17];
    const float* b_s2 = (const float*)d_in[18];
    const float* W_lift = (const float*)d_in[19];
    const float* b_lift = (const float*)d_in[20];
    const float* Wg1 = (const float*)d_in[21];
    const float* bg1 = (const float*)d_in[22];
    const float* Wg2 = (const float*)d_in[23];
    const float* bg2 = (const float*)d_in[24];
    const float* Wc1 = (const float*)d_in[25];
    const float* bc1 = (const float*)d_in[26];
    const float* Wc2 = (const float*)d_in[27];
    const float* bc2 = (const float*)d_in[28];
    const float* norm_scale = (const float*)d_in[29];
    const float* rotors = (const float*)d_in[30];

    float* out = (float*)d_out;
    float* out_ns     = out;
    float* out_newhyp = out + (size_t)B_ * N_ * D_;
    float* out_R      = out_newhyp + B_ * K_ * 4;
    float* out_fim    = out_R + B_ * 16;
    float* out_w      = out_fim + B_ * K_;
    float* out_gate   = out_w + B_ * K_;

    proj_kernel<<<(B_ * N_ * 4) / 128, 128>>>(state, Wq, bq, Wk, bk, hyp, W_hyp, b_hyp);
    attn_kernel<<<dim3(N_ / 128, B_, MSPLIT_), 256>>>();
    attn_epi<<<dim3(N_ / 128, B_), 128>>>(v_gains);
    cand_kernel<<<dim3(N_ / 256, K_, B_), 256>>>(W_act, b_act);
    final_kernel<<<dim3(N_ / 256, B_), 256>>>(state, hyp, R_accum, W_ws, b_ws,
                                              W_s1, b_s1, W_s2, b_s2, W_lift, b_lift, rotors,
                                              Wg1, bg1, Wg2, bg2, Wc1, bc1, Wc2, bc2, norm_scale,
                                              out_ns, out_newhyp, out_R, out_fim, out_w, out_gate);
}